// round 15
// baseline (speedup 1.0000x reference)
#include <cuda_runtime.h>
#include <cuda_fp16.h>
#include <math.h>
#include <stdint.h>

#define BB 16
#define NN 1024
#define KK 16
#define EE 4
#define D0 128
#define HH 256
#define PP 10
#define EPSF 1.1920928955078125e-07f

#define NCH1 16
#define MTILES 128         // BB*NN/128

// ---------------- device scratch (allocation-free rule) --------------------
__device__ __half g_Af[MTILES*NCH1*128*64];       // A tiled fp16, swizzled
__device__ __half g_Bh0[8*256*64];                // B fp16 [256][Kd] tiled
__device__ __half g_Bh1[16*256*64];
__device__ __half g_stateh[BB*NN*HH];             // fp16 states (agg fill)
__device__ float  g_pool[MTILES*PP];

// ---------------- PTX helpers ----------------------------------------------
__device__ __forceinline__ uint32_t smem_u32(const void* p){
    uint32_t a; asm("{ .reg .u64 t; cvta.to.shared.u64 t, %1; cvt.u32.u64 %0, t; }" : "=r"(a) : "l"(p));
    return a;
}
#define MBAR_INIT(mb, c)  asm volatile("mbarrier.init.shared.b64 [%0], %1;" :: "r"((uint32_t)(mb)), "r"((uint32_t)(c)) : "memory")
#define MBAR_EXPECT(mb, tx) asm volatile("mbarrier.arrive.expect_tx.shared.b64 _, [%0], %1;" :: "r"((uint32_t)(mb)), "r"((uint32_t)(tx)) : "memory")
#define MBAR_WAIT(mb, ph) do { \
    uint32_t _m = (uint32_t)(mb), _p = (uint32_t)(ph), _d; \
    asm volatile("{\n\t.reg .pred p;\n\tmbarrier.try_wait.parity.acquire.cta.shared::cta.b64 p, [%1], %2;\n\tselp.b32 %0, 1, 0, p;\n\t}" \
        : "=r"(_d) : "r"(_m), "r"(_p) : "memory"); \
    if (!_d) { \
        asm volatile("{\n\t.reg .pred P1;\n\tWL_%=:\n\tmbarrier.try_wait.parity.acquire.cta.shared::cta.b64 P1, [%0], %1, 0x989680;\n\t@P1 bra.uni WD_%=;\n\tbra.uni WL_%=;\n\tWD_%=:\n\t}" \
            :: "r"(_m), "r"(_p) : "memory"); \
    } } while(0)
#define BULK_G2S(dst, src, bytes, mb) \
    asm volatile("cp.async.bulk.shared::cluster.global.mbarrier::complete_tx::bytes [%0], [%1], %2, [%3];" \
        :: "r"((uint32_t)(dst)), "l"(src), "r"((uint32_t)(bytes)), "r"((uint32_t)(mb)) : "memory")

#define LDMX4(r, a) \
    asm volatile("ldmatrix.sync.aligned.m8n8.x4.shared.b16 {%0,%1,%2,%3}, [%4];" \
        : "=r"((r)[0]), "=r"((r)[1]), "=r"((r)[2]), "=r"((r)[3]) : "r"(a))

__device__ __forceinline__ void mma16816(float* c, const uint32_t* a, uint32_t b0, uint32_t b1){
    asm volatile("mma.sync.aligned.m16n8k16.row.col.f32.f16.f16.f32 "
        "{%0,%1,%2,%3}, {%4,%5,%6,%7}, {%8,%9}, {%0,%1,%2,%3};"
        : "+f"(c[0]), "+f"(c[1]), "+f"(c[2]), "+f"(c[3])
        : "r"(a[0]), "r"(a[1]), "r"(a[2]), "r"(a[3]), "r"(b0), "r"(b1));
}

__device__ __forceinline__ uint32_t tswz(int row, int g){
    return (uint32_t)(row*128 + (((g ^ (row & 7))) << 4));
}

// ---------------------------------------------------------------------------
// 1) Aggregation: LDS.128 gather (4 nodes/warp), direct __ldg(int4) indices.
//    z==zconv blocks convert weights (fp16) for BOTH layers. (unchanged R14)
// ---------------------------------------------------------------------------
#define AGG_SMEM 131072
__global__ __launch_bounds__(1024) void agg_k(const __half* __restrict__ Sh,
        const int* __restrict__ nf, const float* __restrict__ emb,
        const int* __restrict__ nn_idx, const float* __restrict__ mask,
        const float* __restrict__ W0, const float* __restrict__ W1,
        int D, int nch, int useEmb, int nsplit_shift, int zconv){
    extern __shared__ char smraw[];
    __half* sbuf = (__half*)smraw;                  // [1024][64]
    int tid = threadIdx.x, lane = tid & 31, w = tid >> 5;

    if ((int)blockIdx.z == zconv){
        int bid = blockIdx.x * gridDim.y + blockIdx.y;   // 0..31
        for (int t = bid*1024 + tid; t < 49152; t += 32*1024){
            const float* W; __half *Bh; int g;
            if (t < 16384){ W = W0; Bh = g_Bh0; g = t; }
            else          { W = W1; Bh = g_Bh1; g = t - 16384; }
            int n  = g & 255;
            int kq = g >> 8;
            __half hv[8];
            #pragma unroll
            for (int j = 0; j < 8; j++)
                hv[j] = __float2half(W[(size_t)(kq*8 + j)*HH + n]);
            int ch = kq >> 3;
            size_t byt = (((size_t)(ch*256 + n)) << 7) + ((((kq & 7) ^ (n & 7))) << 4);
            *(uint4*)((char*)Bh + byt) = *(uint4*)hv;
        }
        return;
    }

    int b   = blockIdx.x;
    int d0c = blockIdx.y * 64;

    if (useEmb){
        const int* nfb = nf + b*NN;
        for (int i = tid; i < NN*32; i += 1024){
            int row = i >> 5, cp = (i & 31) << 1;
            const float* ep = emb + (size_t)nfb[row]*D0 + d0c + cp;
            float2 v = make_float2(ep[0], ep[1]);
            *(__half2*)&sbuf[row*64 + cp] = __floats2half2_rn(v.x, v.y);
        }
    } else {
        const __half* Sb = Sh + (size_t)b*NN*HH;
        for (int i = tid; i < NN*16; i += 1024){
            int row = i >> 4, cp = (i & 15) << 2;
            *(uint2*)&sbuf[row*64 + cp] = *(const uint2*)&Sb[(size_t)row*HH + d0c + cp];
        }
    }
    __syncthreads();

    int nPer  = NN >> nsplit_shift;
    int nbase = blockIdx.z * nPer;
    char* Ag = (char*)g_Af;
    int p = lane & 7, grp = lane >> 3;

    for (int n0 = nbase + 4*w; n0 < nbase + nPer; n0 += 128){
        int nj = n0 + grp;
        const int4* ip4 = (const int4*)(nn_idx + (size_t)(b*NN + nj)*(KK*EE));
        const __half2* sp = (const __half2*)sbuf + p*4;

        __half2 acc[4][4];
        #pragma unroll
        for (int e = 0; e < 4; e++)
            #pragma unroll
            for (int i = 0; i < 4; i++) acc[e][i] = __float2half2_rn(0.f);

        #pragma unroll 4
        for (int g = 0; g < KK; g++){
            int4 q = __ldg(&ip4[g]);
            uint4 v0 = *(const uint4*)(sp + q.x*32);
            uint4 v1 = *(const uint4*)(sp + q.y*32);
            uint4 v2 = *(const uint4*)(sp + q.z*32);
            uint4 v3 = *(const uint4*)(sp + q.w*32);
            const __half2* h0 = (const __half2*)&v0;
            const __half2* h1 = (const __half2*)&v1;
            const __half2* h2 = (const __half2*)&v2;
            const __half2* h3 = (const __half2*)&v3;
            #pragma unroll
            for (int i = 0; i < 4; i++){
                acc[0][i] = __hadd2(acc[0][i], h0[i]);
                acc[1][i] = __hadd2(acc[1][i], h1[i]);
                acc[2][i] = __hadd2(acc[2][i], h2[i]);
                acc[3][i] = __hadd2(acc[3][i], h3[i]);
            }
        }

        __half2 m2 = __float2half2_rn(mask[b*NN + nj] * 0.0625f);
        int mtile = b*8 + (nj >> 7);
        int mrow  = nj & 127;
        size_t tbase = ((size_t)mtile*nch) << 14;
        uint32_t inrow = (((uint32_t)(p ^ (mrow & 7))) << 4);
        #pragma unroll
        for (int e = 0; e < EE; e++){
            __half2 r[4];
            #pragma unroll
            for (int i = 0; i < 4; i++) r[i] = __hmul2(acc[e][i], m2);
            int ch = (e*D + d0c) >> 6;
            *(uint4*)(Ag + tbase + (((size_t)ch*128 + mrow) << 7) + inrow) = *(uint4*)r;
        }
    }
}

// ---------------------------------------------------------------------------
// 2) GEMM: single-pass fp16, 3-stage cp.async.bulk pipeline, 128x256 tile,
//    1024 threads / 32 warps (warp tile 32x32) for 2x latency hiding.
// ---------------------------------------------------------------------------
#define STG48 49152
#define EPI_STR 258
// epilogue extras above the 3-stage region (3*49152 = 147456)
#define OFF_WA   147456
#define OFF_WT   148480      // [256][12] floats = 12288
#define OFF_ZRED 160768      // [16][264] floats = 16896
#define OFF_ARED 177664      // 16 floats
#define OFF_ZFIN 177728      // 256 floats -> 178752
#define MB_OFF   178752      // 3 mbars
#define GEMM_SMEM 178816

__global__ __launch_bounds__(1024, 1) void gemm2_k(
        const __half* __restrict__ Agl, const __half* __restrict__ Bhg,
        int nch, const float* __restrict__ bias, __half* __restrict__ Sout,
        int fuse, const float* __restrict__ Wout, const float* __restrict__ bout,
        const float* __restrict__ Watt, const float* __restrict__ batt){
    extern __shared__ char smx[];
    uint32_t sb0 = smem_u32(smx);
    uint32_t mb  = sb0 + MB_OFF;
    int tid = threadIdx.x, lane = tid & 31, w = tid >> 5;
    int wm = w >> 3, wn = w & 7;              // wm 0..3 (32 rows), wn 0..7 (32 cols)
    int mtile = blockIdx.x;

    if (tid == 0){ MBAR_INIT(mb, 1); MBAR_INIT(mb + 8, 1); MBAR_INIT(mb + 16, 1); }
    __syncthreads();

    float c[2][4][4];
    #pragma unroll
    for (int mi = 0; mi < 2; mi++)
        #pragma unroll
        for (int cj = 0; cj < 4; cj++)
            #pragma unroll
            for (int q = 0; q < 4; q++) c[mi][cj][q] = 0.f;

    auto issue = [&](int ch){
        int st = ch % 3;
        uint32_t d = sb0 + st*STG48;
        uint32_t m = mb + st*8;
        MBAR_EXPECT(m, STG48);
        BULK_G2S(d,         (const char*)Agl + (((size_t)(mtile*nch + ch)) << 14), 16384, m);
        BULK_G2S(d + 16384, (const char*)Bhg + (((size_t)ch) << 15),               32768, m);
    };

    if (tid == 0){ issue(0); issue(1); issue(2); }
    int ph[3] = {0, 0, 0};

    int lrow = lane & 15;
    for (int ch = 0; ch < nch; ch++){
        int st = ch % 3;
        MBAR_WAIT(mb + st*8, ph[st]); ph[st] ^= 1;

        uint32_t ab = sb0 + st*STG48;
        uint32_t bh = ab + 16384;
        #pragma unroll
        for (int s = 0; s < 4; s++){
            int g = 2*s + (lane >> 4);
            uint32_t a[2][4], bq[2][4];
            #pragma unroll
            for (int mi = 0; mi < 2; mi++)
                LDMX4(a[mi], ab + tswz(wm*32 + mi*16 + lrow, g));
            #pragma unroll
            for (int nj = 0; nj < 2; nj++)
                LDMX4(bq[nj], bh + tswz(wn*32 + nj*16 + lrow, g));
            #pragma unroll
            for (int mi = 0; mi < 2; mi++)
                #pragma unroll
                for (int nj = 0; nj < 2; nj++){
                    mma16816(c[mi][2*nj+0], a[mi], bq[nj][0], bq[nj][2]);
                    mma16816(c[mi][2*nj+1], a[mi], bq[nj][1], bq[nj][3]);
                }
        }
        __syncthreads();
        if (tid == 0 && ch + 3 < nch) issue(ch + 3);
    }
    __syncthreads();

    // --- Phase A: bias + relu into sbuf; head weights into smem (fuse) ---
    float* sbuf = (float*)smx;
    int qr = lane >> 2, qc = (lane & 3)*2;
    #pragma unroll
    for (int mi = 0; mi < 2; mi++){
        int r0 = wm*32 + mi*16 + qr;
        #pragma unroll
        for (int cj = 0; cj < 4; cj++){
            int col = wn*32 + cj*8 + qc;
            float b0 = bias[col], b1 = bias[col+1];
            *(float2*)&sbuf[(size_t)r0*EPI_STR + col] =
                make_float2(fmaxf(c[mi][cj][0] + b0, 0.f), fmaxf(c[mi][cj][1] + b1, 0.f));
            *(float2*)&sbuf[(size_t)(r0+8)*EPI_STR + col] =
                make_float2(fmaxf(c[mi][cj][2] + b0, 0.f), fmaxf(c[mi][cj][3] + b1, 0.f));
        }
    }
    float* wa = (float*)(smx + OFF_WA);
    float* wt = (float*)(smx + OFF_WT);
    if (fuse){
        if (tid < 256) wa[tid] = Watt[tid];
        for (int i = tid; i < 256*PP; i += 1024){
            int d = i / PP, p2 = i - d*PP;
            wt[d*12 + p2] = Wout[i];
        }
    }
    __syncthreads();

    // --- Phase B ---
    int m0 = mtile*128;
    if (!fuse){
        #pragma unroll
        for (int r = 0; r < 4; r++){
            int row = w*4 + r;
            const float2* rp2 = (const float2*)&sbuf[(size_t)row*EPI_STR];
            float2 v2[4]; float ss = 0.f;
            #pragma unroll
            for (int j = 0; j < 4; j++){
                v2[j] = rp2[lane + 32*j];
                ss += v2[j].x*v2[j].x + v2[j].y*v2[j].y;
            }
            #pragma unroll
            for (int off = 16; off; off >>= 1) ss += __shfl_xor_sync(0xffffffffu, ss, off);
            float inv = 1.0f/(sqrtf(ss) + EPSF);
            __half2* oph = (__half2*)(Sout + (size_t)(m0 + row)*HH);
            #pragma unroll
            for (int j = 0; j < 4; j++)
                oph[lane + 32*j] = __floats2half2_rn(v2[j].x*inv, v2[j].y*inv);
        }
    } else {
        float* zred = (float*)(smx + OFF_ZRED);
        float* ared = (float*)(smx + OFF_ARED);
        float* zfin = (float*)(smx + OFF_ZFIN);
        if (w < 16){
            float ba = batt[0];
            float2 zacc[4];
            #pragma unroll
            for (int j = 0; j < 4; j++) zacc[j] = make_float2(0.f, 0.f);
            float Aacc = 0.f;
            #pragma unroll
            for (int r = 0; r < 8; r++){
                int row = w*8 + r;
                const float2* rp2 = (const float2*)&sbuf[(size_t)row*EPI_STR];
                float2 v2[4]; float ss = 0.f;
                #pragma unroll
                for (int j = 0; j < 4; j++){
                    v2[j] = rp2[lane + 32*j];
                    ss += v2[j].x*v2[j].x + v2[j].y*v2[j].y;
                }
                #pragma unroll
                for (int off = 16; off; off >>= 1) ss += __shfl_xor_sync(0xffffffffu, ss, off);
                float inv = 1.0f/(sqrtf(ss) + EPSF);
                float att = 0.f;
                #pragma unroll
                for (int j = 0; j < 4; j++){
                    int c0 = 2*lane + 64*j;
                    att += v2[j].x*inv*wa[c0] + v2[j].y*inv*wa[c0+1];
                }
                #pragma unroll
                for (int off = 16; off; off >>= 1) att += __shfl_xor_sync(0xffffffffu, att, off);
                float a = 1.0f/(1.0f + expf(-(att + ba)));
                float ai = a * inv;
                #pragma unroll
                for (int j = 0; j < 4; j++){
                    zacc[j].x += ai * v2[j].x;
                    zacc[j].y += ai * v2[j].y;
                }
                Aacc += a;
            }
            #pragma unroll
            for (int j = 0; j < 4; j++)
                *(float2*)&zred[w*264 + 2*lane + 64*j] = zacc[j];
            if (lane == 0) ared[w] = Aacc;
        }
        __syncthreads();
        if (tid < 256){
            float s = 0.f;
            #pragma unroll
            for (int w2 = 0; w2 < 16; w2++) s += zred[w2*264 + tid];
            zfin[tid] = s;
        }
        __syncthreads();
        if (tid < PP){
            float A = 0.f;
            #pragma unroll
            for (int w2 = 0; w2 < 16; w2++) A += ared[w2];
            float sc = A * bout[tid];
            for (int d = 0; d < 256; d++) sc += zfin[d] * wt[d*12 + tid];
            g_pool[mtile*PP + tid] = sc;
        }
    }
}

// ---------------------------------------------------------------------------
// 3) Final reduce
// ---------------------------------------------------------------------------
__global__ void reduce_k(float* __restrict__ out){
    int i = threadIdx.x;
    if (i < BB*PP){
        int b = i / PP, p = i - b*PP;
        float s = 0.f;
        #pragma unroll
        for (int seg = 0; seg < 8; seg++) s += g_pool[(b*8 + seg)*PP + p];
        out[i] = s * (1.0f/NN);
    }
}

// ---------------------------------------------------------------------------
extern "C" void kernel_launch(void* const* d_in, const int* in_sizes, int n_in,
                              void* d_out, int out_size){
    (void)in_sizes; (void)n_in; (void)out_size;
    const int*   nf   = (const int*)  d_in[0];
    const int*   nn   = (const int*)  d_in[1];
    const float* mask = (const float*)d_in[2];
    const float* emb  = (const float*)d_in[3];
    const float* W0   = (const float*)d_in[4];
    const float* b0   = (const float*)d_in[5];
    const float* W1   = (const float*)d_in[6];
    const float* b1   = (const float*)d_in[7];
    const float* Wout = (const float*)d_in[8];
    const float* bout = (const float*)d_in[9];
    const float* Watt = (const float*)d_in[10];
    const float* batt = (const float*)d_in[11];
    float* out = (float*)d_out;

    __half *stateh, *af, *bh0, *bh1;
    cudaGetSymbolAddress((void**)&stateh, g_stateh);
    cudaGetSymbolAddress((void**)&af,  g_Af);
    cudaGetSymbolAddress((void**)&bh0, g_Bh0);
    cudaGetSymbolAddress((void**)&bh1, g_Bh1);

    cudaFuncSetAttribute(agg_k,   cudaFuncAttributeMaxDynamicSharedMemorySize, AGG_SMEM);
    cudaFuncSetAttribute(gemm2_k, cudaFuncAttributeMaxDynamicSharedMemorySize, GEMM_SMEM);

    // Layer 0 (Kd=512, nch=8): embed fused, z-split 4; z==4 converts weights
    agg_k<<<dim3(BB, D0/64, 5), 1024, AGG_SMEM>>>(stateh, nf, emb, nn, mask,
                                                  W0, W1, D0, 8, 1, 2, 4);
    gemm2_k<<<MTILES, 1024, GEMM_SMEM>>>(af, bh0, 8, b0, stateh,
                                         0, nullptr, nullptr, nullptr, nullptr);

    // Layer 1 (Kd=1024, nch=16): z-split 2; fused output head
    agg_k<<<dim3(BB, HH/64, 2), 1024, AGG_SMEM>>>(stateh, nf, emb, nn, mask,
                                                  W0, W1, HH, 16, 0, 1, -1);
    gemm2_k<<<MTILES, 1024, GEMM_SMEM>>>(af, bh1, 16, b1, stateh,
                                         1, Wout, bout, Watt, batt);

    reduce_k<<<1, 192>>>(out);
}

// round 16
// speedup vs baseline: 1.0826x; 1.0826x over previous
#include <cuda_runtime.h>
#include <cuda_fp16.h>
#include <math.h>
#include <stdint.h>

#define BB 16
#define NN 1024
#define KK 16
#define EE 4
#define D0 128
#define HH 256
#define PP 10
#define EPSF 1.1920928955078125e-07f

#define NCH1 16
#define MTILES 128         // BB*NN/128

// ---------------- device scratch (allocation-free rule) --------------------
__device__ __half g_Af[MTILES*NCH1*128*64];       // A tiled fp16, swizzled
__device__ __half g_Bh0[8*256*64];                // B fp16 [256][Kd] tiled
__device__ __half g_Bh1[16*256*64];
__device__ __half g_stateh[BB*NN*HH];             // fp16 states (agg fill)
__device__ float  g_pool[MTILES*PP];

// ---------------- PTX helpers ----------------------------------------------
__device__ __forceinline__ uint32_t smem_u32(const void* p){
    uint32_t a; asm("{ .reg .u64 t; cvta.to.shared.u64 t, %1; cvt.u32.u64 %0, t; }" : "=r"(a) : "l"(p));
    return a;
}
#define MBAR_INIT(mb, c)  asm volatile("mbarrier.init.shared.b64 [%0], %1;" :: "r"((uint32_t)(mb)), "r"((uint32_t)(c)) : "memory")
#define MBAR_EXPECT(mb, tx) asm volatile("mbarrier.arrive.expect_tx.shared.b64 _, [%0], %1;" :: "r"((uint32_t)(mb)), "r"((uint32_t)(tx)) : "memory")
#define MBAR_WAIT(mb, ph) do { \
    uint32_t _m = (uint32_t)(mb), _p = (uint32_t)(ph), _d; \
    asm volatile("{\n\t.reg .pred p;\n\tmbarrier.try_wait.parity.acquire.cta.shared::cta.b64 p, [%1], %2;\n\tselp.b32 %0, 1, 0, p;\n\t}" \
        : "=r"(_d) : "r"(_m), "r"(_p) : "memory"); \
    if (!_d) { \
        asm volatile("{\n\t.reg .pred P1;\n\tWL_%=:\n\tmbarrier.try_wait.parity.acquire.cta.shared::cta.b64 P1, [%0], %1, 0x989680;\n\t@P1 bra.uni WD_%=;\n\tbra.uni WL_%=;\n\tWD_%=:\n\t}" \
            :: "r"(_m), "r"(_p) : "memory"); \
    } } while(0)
#define BULK_G2S(dst, src, bytes, mb) \
    asm volatile("cp.async.bulk.shared::cluster.global.mbarrier::complete_tx::bytes [%0], [%1], %2, [%3];" \
        :: "r"((uint32_t)(dst)), "l"(src), "r"((uint32_t)(bytes)), "r"((uint32_t)(mb)) : "memory")

#define LDMX4(r, a) \
    asm volatile("ldmatrix.sync.aligned.m8n8.x4.shared.b16 {%0,%1,%2,%3}, [%4];" \
        : "=r"((r)[0]), "=r"((r)[1]), "=r"((r)[2]), "=r"((r)[3]) : "r"(a))

__device__ __forceinline__ void mma16816(float* c, const uint32_t* a, uint32_t b0, uint32_t b1){
    asm volatile("mma.sync.aligned.m16n8k16.row.col.f32.f16.f16.f32 "
        "{%0,%1,%2,%3}, {%4,%5,%6,%7}, {%8,%9}, {%0,%1,%2,%3};"
        : "+f"(c[0]), "+f"(c[1]), "+f"(c[2]), "+f"(c[3])
        : "r"(a[0]), "r"(a[1]), "r"(a[2]), "r"(a[3]), "r"(b0), "r"(b1));
}

__device__ __forceinline__ uint32_t tswz(int row, int g){
    return (uint32_t)(row*128 + (((g ^ (row & 7))) << 4));
}

// ---------------------------------------------------------------------------
// 1) Aggregation: LDS.128 gather (4 nodes/warp), direct __ldg(int4) indices.
//    z==zconv blocks convert weights (fp16) for BOTH layers. (unchanged R14)
// ---------------------------------------------------------------------------
#define AGG_SMEM 131072
__global__ __launch_bounds__(1024) void agg_k(const __half* __restrict__ Sh,
        const int* __restrict__ nf, const float* __restrict__ emb,
        const int* __restrict__ nn_idx, const float* __restrict__ mask,
        const float* __restrict__ W0, const float* __restrict__ W1,
        int D, int nch, int useEmb, int nsplit_shift, int zconv){
    extern __shared__ char smraw[];
    __half* sbuf = (__half*)smraw;                  // [1024][64]
    int tid = threadIdx.x, lane = tid & 31, w = tid >> 5;

    if ((int)blockIdx.z == zconv){
        int bid = blockIdx.x * gridDim.y + blockIdx.y;   // 0..31
        for (int t = bid*1024 + tid; t < 49152; t += 32*1024){
            const float* W; __half *Bh; int g;
            if (t < 16384){ W = W0; Bh = g_Bh0; g = t; }
            else          { W = W1; Bh = g_Bh1; g = t - 16384; }
            int n  = g & 255;
            int kq = g >> 8;
            __half hv[8];
            #pragma unroll
            for (int j = 0; j < 8; j++)
                hv[j] = __float2half(W[(size_t)(kq*8 + j)*HH + n]);
            int ch = kq >> 3;
            size_t byt = (((size_t)(ch*256 + n)) << 7) + ((((kq & 7) ^ (n & 7))) << 4);
            *(uint4*)((char*)Bh + byt) = *(uint4*)hv;
        }
        return;
    }

    int b   = blockIdx.x;
    int d0c = blockIdx.y * 64;

    if (useEmb){
        const int* nfb = nf + b*NN;
        for (int i = tid; i < NN*32; i += 1024){
            int row = i >> 5, cp = (i & 31) << 1;
            const float* ep = emb + (size_t)nfb[row]*D0 + d0c + cp;
            float2 v = make_float2(ep[0], ep[1]);
            *(__half2*)&sbuf[row*64 + cp] = __floats2half2_rn(v.x, v.y);
        }
    } else {
        const __half* Sb = Sh + (size_t)b*NN*HH;
        for (int i = tid; i < NN*16; i += 1024){
            int row = i >> 4, cp = (i & 15) << 2;
            *(uint2*)&sbuf[row*64 + cp] = *(const uint2*)&Sb[(size_t)row*HH + d0c + cp];
        }
    }
    __syncthreads();

    int nPer  = NN >> nsplit_shift;
    int nbase = blockIdx.z * nPer;
    char* Ag = (char*)g_Af;
    int p = lane & 7, grp = lane >> 3;

    for (int n0 = nbase + 4*w; n0 < nbase + nPer; n0 += 128){
        int nj = n0 + grp;
        const int4* ip4 = (const int4*)(nn_idx + (size_t)(b*NN + nj)*(KK*EE));
        const __half2* sp = (const __half2*)sbuf + p*4;

        __half2 acc[4][4];
        #pragma unroll
        for (int e = 0; e < 4; e++)
            #pragma unroll
            for (int i = 0; i < 4; i++) acc[e][i] = __float2half2_rn(0.f);

        #pragma unroll 4
        for (int g = 0; g < KK; g++){
            int4 q = __ldg(&ip4[g]);
            uint4 v0 = *(const uint4*)(sp + q.x*32);
            uint4 v1 = *(const uint4*)(sp + q.y*32);
            uint4 v2 = *(const uint4*)(sp + q.z*32);
            uint4 v3 = *(const uint4*)(sp + q.w*32);
            const __half2* h0 = (const __half2*)&v0;
            const __half2* h1 = (const __half2*)&v1;
            const __half2* h2 = (const __half2*)&v2;
            const __half2* h3 = (const __half2*)&v3;
            #pragma unroll
            for (int i = 0; i < 4; i++){
                acc[0][i] = __hadd2(acc[0][i], h0[i]);
                acc[1][i] = __hadd2(acc[1][i], h1[i]);
                acc[2][i] = __hadd2(acc[2][i], h2[i]);
                acc[3][i] = __hadd2(acc[3][i], h3[i]);
            }
        }

        __half2 m2 = __float2half2_rn(mask[b*NN + nj] * 0.0625f);
        int mtile = b*8 + (nj >> 7);
        int mrow  = nj & 127;
        size_t tbase = ((size_t)mtile*nch) << 14;
        uint32_t inrow = (((uint32_t)(p ^ (mrow & 7))) << 4);
        #pragma unroll
        for (int e = 0; e < EE; e++){
            __half2 r[4];
            #pragma unroll
            for (int i = 0; i < 4; i++) r[i] = __hmul2(acc[e][i], m2);
            int ch = (e*D + d0c) >> 6;
            *(uint4*)(Ag + tbase + (((size_t)ch*128 + mrow) << 7) + inrow) = *(uint4*)r;
        }
    }
}

// ---------------------------------------------------------------------------
// 2) GEMM: single-pass fp16, 3-stage cp.async.bulk pipeline, 128x256 tile,
//    512 thr / 16 warps (warp tile 64x32), B-fragment double-buffering,
//    register-resident epilogue (no 132KB staging buffer).
// ---------------------------------------------------------------------------
#define STG48 49152
// extras above the 3-stage region (3*49152 = 147456)
#define OFF_SSB  147456      // [128][9] floats = 4608
#define OFF_INV  152064      // 128 floats
#define OFF_AB   152576      // 128 floats
#define OFF_WA   153088      // 256 floats
#define OFF_WT   154112      // 256*12 floats = 12288
#define OFF_ZW   166400      // [16][36] floats = 2304
#define OFF_ZF   168704      // 256 floats
#define MB_OFF   169728      // 3 mbars
#define GEMM_SMEM 169792

__global__ __launch_bounds__(512, 1) void gemm2_k(
        const __half* __restrict__ Agl, const __half* __restrict__ Bhg,
        int nch, const float* __restrict__ bias, __half* __restrict__ Sout,
        int fuse, const float* __restrict__ Wout, const float* __restrict__ bout,
        const float* __restrict__ Watt, const float* __restrict__ batt){
    extern __shared__ char smx[];
    uint32_t sb0 = smem_u32(smx);
    uint32_t mb  = sb0 + MB_OFF;
    int tid = threadIdx.x, lane = tid & 31, w = tid >> 5;
    int wm = w >> 3, wn = w & 7;
    int mtile = blockIdx.x;

    if (tid == 0){ MBAR_INIT(mb, 1); MBAR_INIT(mb + 8, 1); MBAR_INIT(mb + 16, 1); }
    __syncthreads();

    float c[4][4][4];
    #pragma unroll
    for (int mi = 0; mi < 4; mi++)
        #pragma unroll
        for (int nj = 0; nj < 4; nj++)
            #pragma unroll
            for (int q = 0; q < 4; q++) c[mi][nj][q] = 0.f;

    auto issue = [&](int ch){
        int st = ch % 3;
        uint32_t d = sb0 + st*STG48;
        uint32_t m = mb + st*8;
        MBAR_EXPECT(m, STG48);
        BULK_G2S(d,         (const char*)Agl + (((size_t)(mtile*nch + ch)) << 14), 16384, m);
        BULK_G2S(d + 16384, (const char*)Bhg + (((size_t)ch) << 15),               32768, m);
    };

    if (tid == 0){ issue(0); issue(1); issue(2); }
    int ph[3] = {0, 0, 0};

    int lrow = lane & 15;
    int ghalf = lane >> 4;
    for (int ch = 0; ch < nch; ch++){
        int st = ch % 3;
        MBAR_WAIT(mb + st*8, ph[st]); ph[st] ^= 1;

        uint32_t ab = sb0 + st*STG48;
        uint32_t bh = ab + 16384;

        uint32_t bq[2][2][4];                    // [nj][buf][4]
        {   // preload B frags for s=0
            LDMX4(bq[0][0], bh + tswz(wn*32 + lrow,      ghalf));
            LDMX4(bq[1][0], bh + tswz(wn*32 + 16 + lrow, ghalf));
        }
        #pragma unroll
        for (int s = 0; s < 4; s++){
            int cur = s & 1;
            if (s < 3){                          // prefetch B for s+1
                int gn = 2*(s+1) + ghalf;
                LDMX4(bq[0][cur^1], bh + tswz(wn*32 + lrow,      gn));
                LDMX4(bq[1][cur^1], bh + tswz(wn*32 + 16 + lrow, gn));
            }
            int g = 2*s + ghalf;
            uint32_t a[4][4];
            #pragma unroll
            for (int mi = 0; mi < 4; mi++)
                LDMX4(a[mi], ab + tswz(wm*64 + mi*16 + lrow, g));
            #pragma unroll
            for (int mi = 0; mi < 4; mi++)
                #pragma unroll
                for (int nj = 0; nj < 2; nj++){
                    mma16816(c[mi][2*nj+0], a[mi], bq[nj][cur][0], bq[nj][cur][2]);
                    mma16816(c[mi][2*nj+1], a[mi], bq[nj][cur][1], bq[nj][cur][3]);
                }
        }
        __syncthreads();
        if (tid == 0 && ch + 3 < nch) issue(ch + 3);
    }

    // ---- register-resident epilogue ----
    float* ssb  = (float*)(smx + OFF_SSB);
    float* invb = (float*)(smx + OFF_INV);
    float* ab_  = (float*)(smx + OFF_AB);
    float* wa   = (float*)(smx + OFF_WA);
    float* wt   = (float*)(smx + OFF_WT);
    int qr = lane >> 2, qc = (lane & 3)*2;

    // bias + relu in accumulators; ssq partials per (row, wn)
    float ssq[4][2];
    #pragma unroll
    for (int mi = 0; mi < 4; mi++){ ssq[mi][0] = 0.f; ssq[mi][1] = 0.f; }
    #pragma unroll
    for (int mi = 0; mi < 4; mi++)
        #pragma unroll
        for (int nj = 0; nj < 4; nj++){
            int col = wn*32 + nj*8 + qc;
            float b0 = bias[col], b1 = bias[col+1];
            #pragma unroll
            for (int qh = 0; qh < 2; qh++){
                float h0 = fmaxf(c[mi][nj][2*qh+0] + b0, 0.f);
                float h1 = fmaxf(c[mi][nj][2*qh+1] + b1, 0.f);
                c[mi][nj][2*qh+0] = h0;
                c[mi][nj][2*qh+1] = h1;
                ssq[mi][qh] += h0*h0 + h1*h1;
            }
        }
    #pragma unroll
    for (int mi = 0; mi < 4; mi++)
        #pragma unroll
        for (int qh = 0; qh < 2; qh++){
            float v = ssq[mi][qh];
            v += __shfl_xor_sync(0xffffffffu, v, 1);
            v += __shfl_xor_sync(0xffffffffu, v, 2);
            if ((lane & 3) == 0)
                ssb[(wm*64 + mi*16 + qr + 8*qh)*9 + wn] = v;
        }
    if (fuse){
        if (tid < 256) wa[tid] = Watt[tid];
        for (int i = tid; i < 256*PP; i += 512){
            int d = i / PP, p2 = i - d*PP;
            wt[d*12 + p2] = Wout[i];
        }
    }
    __syncthreads();
    if (tid < 128){
        float s = 0.f;
        #pragma unroll
        for (int j = 0; j < 8; j++) s += ssb[tid*9 + j];
        invb[tid] = 1.0f/(sqrtf(s) + EPSF);
    }
    __syncthreads();

    int m0 = mtile*128;
    if (!fuse){
        #pragma unroll
        for (int mi = 0; mi < 4; mi++)
            #pragma unroll
            for (int qh = 0; qh < 2; qh++){
                int row = wm*64 + mi*16 + qr + 8*qh;
                float inv = invb[row];
                __half* op = Sout + (size_t)(m0 + row)*HH;
                #pragma unroll
                for (int nj = 0; nj < 4; nj++){
                    int col = wn*32 + nj*8 + qc;
                    *(__half2*)(op + col) =
                        __floats2half2_rn(c[mi][nj][2*qh]*inv, c[mi][nj][2*qh+1]*inv);
                }
            }
    } else {
        float* zw = (float*)(smx + OFF_ZW);
        float* zf = (float*)(smx + OFF_ZF);
        // att raw-dot partials into ssb (invb already consumed & synced)
        #pragma unroll
        for (int mi = 0; mi < 4; mi++)
            #pragma unroll
            for (int qh = 0; qh < 2; qh++){
                int row = wm*64 + mi*16 + qr + 8*qh;
                float at = 0.f;
                #pragma unroll
                for (int nj = 0; nj < 4; nj++){
                    int col = wn*32 + nj*8 + qc;
                    at += c[mi][nj][2*qh]*wa[col] + c[mi][nj][2*qh+1]*wa[col+1];
                }
                at += __shfl_xor_sync(0xffffffffu, at, 1);
                at += __shfl_xor_sync(0xffffffffu, at, 2);
                if ((lane & 3) == 0) ssb[row*9 + wn] = at;
            }
        __syncthreads();
        if (tid < 128){
            float at = 0.f;
            #pragma unroll
            for (int j = 0; j < 8; j++) at += ssb[tid*9 + j];
            ab_[tid] = 1.0f/(1.0f + expf(-(invb[tid]*at + batt[0])));
        }
        __syncthreads();
        // z[col] = sum_rows a*inv*h  (per-thread over its 8 rows, shfl over qr)
        float2 z2[4];
        #pragma unroll
        for (int nj = 0; nj < 4; nj++) z2[nj] = make_float2(0.f, 0.f);
        #pragma unroll
        for (int mi = 0; mi < 4; mi++)
            #pragma unroll
            for (int qh = 0; qh < 2; qh++){
                int row = wm*64 + mi*16 + qr + 8*qh;
                float cf = ab_[row]*invb[row];
                #pragma unroll
                for (int nj = 0; nj < 4; nj++){
                    z2[nj].x += cf*c[mi][nj][2*qh];
                    z2[nj].y += cf*c[mi][nj][2*qh+1];
                }
            }
        #pragma unroll
        for (int nj = 0; nj < 4; nj++){
            #pragma unroll
            for (int off = 4; off < 32; off <<= 1){
                z2[nj].x += __shfl_xor_sync(0xffffffffu, z2[nj].x, off);
                z2[nj].y += __shfl_xor_sync(0xffffffffu, z2[nj].y, off);
            }
        }
        if (lane < 4){
            #pragma unroll
            for (int nj = 0; nj < 4; nj++)
                *(float2*)&zw[w*36 + nj*8 + lane*2] = z2[nj];
        }
        __syncthreads();
        if (tid < 256){
            int wn2 = tid >> 5, cc = tid & 31;
            zf[tid] = zw[(wn2)*36 + cc] + zw[(8 + wn2)*36 + cc];
        }
        __syncthreads();
        if (tid < PP){
            float A = 0.f;
            #pragma unroll
            for (int r = 0; r < 128; r++) A += ab_[r];
            float sc = A * bout[tid];
            for (int d = 0; d < 256; d++) sc += zf[d] * wt[d*12 + tid];
            g_pool[mtile*PP + tid] = sc;
        }
    }
}

// ---------------------------------------------------------------------------
// 3) Final reduce
// ---------------------------------------------------------------------------
__global__ void reduce_k(float* __restrict__ out){
    int i = threadIdx.x;
    if (i < BB*PP){
        int b = i / PP, p = i - b*PP;
        float s = 0.f;
        #pragma unroll
        for (int seg = 0; seg < 8; seg++) s += g_pool[(b*8 + seg)*PP + p];
        out[i] = s * (1.0f/NN);
    }
}

// ---------------------------------------------------------------------------
extern "C" void kernel_launch(void* const* d_in, const int* in_sizes, int n_in,
                              void* d_out, int out_size){
    (void)in_sizes; (void)n_in; (void)out_size;
    const int*   nf   = (const int*)  d_in[0];
    const int*   nn   = (const int*)  d_in[1];
    const float* mask = (const float*)d_in[2];
    const float* emb  = (const float*)d_in[3];
    const float* W0   = (const float*)d_in[4];
    const float* b0   = (const float*)d_in[5];
    const float* W1   = (const float*)d_in[6];
    const float* b1   = (const float*)d_in[7];
    const float* Wout = (const float*)d_in[8];
    const float* bout = (const float*)d_in[9];
    const float* Watt = (const float*)d_in[10];
    const float* batt = (const float*)d_in[11];
    float* out = (float*)d_out;

    __half *stateh, *af, *bh0, *bh1;
    cudaGetSymbolAddress((void**)&stateh, g_stateh);
    cudaGetSymbolAddress((void**)&af,  g_Af);
    cudaGetSymbolAddress((void**)&bh0, g_Bh0);
    cudaGetSymbolAddress((void**)&bh1, g_Bh1);

    cudaFuncSetAttribute(agg_k,   cudaFuncAttributeMaxDynamicSharedMemorySize, AGG_SMEM);
    cudaFuncSetAttribute(gemm2_k, cudaFuncAttributeMaxDynamicSharedMemorySize, GEMM_SMEM);

    // Layer 0 (Kd=512, nch=8): embed fused, z-split 4; z==4 converts weights
    agg_k<<<dim3(BB, D0/64, 5), 1024, AGG_SMEM>>>(stateh, nf, emb, nn, mask,
                                                  W0, W1, D0, 8, 1, 2, 4);
    gemm2_k<<<MTILES, 512, GEMM_SMEM>>>(af, bh0, 8, b0, stateh,
                                        0, nullptr, nullptr, nullptr, nullptr);

    // Layer 1 (Kd=1024, nch=16): z-split 2; fused output head
    agg_k<<<dim3(BB, HH/64, 2), 1024, AGG_SMEM>>>(stateh, nf, emb, nn, mask,
                                                  W0, W1, HH, 16, 0, 1, -1);
    gemm2_k<<<MTILES, 512, GEMM_SMEM>>>(af, bh1, 16, b1, stateh,
                                        1, Wout, bout, Watt, batt);

    reduce_k<<<1, 192>>>(out);
}

// round 17
// speedup vs baseline: 1.1059x; 1.0215x over previous
#include <cuda_runtime.h>
#include <cuda_fp16.h>
#include <math.h>
#include <stdint.h>

#define BB 16
#define NN 1024
#define KK 16
#define EE 4
#define D0 128
#define HH 256
#define PP 10
#define EPSF 1.1920928955078125e-07f

#define NCH1 16
#define MTILES 128         // BB*NN/128

// ---------------- device scratch (allocation-free rule) --------------------
__device__ __half g_Af[MTILES*NCH1*128*64];       // A tiled fp16, swizzled
__device__ __half g_Bh0[8*256*64];                // B fp16 [256][Kd] tiled
__device__ __half g_Bh1[16*256*64];
__device__ __half g_stateh[BB*NN*HH];             // fp16 states (agg fill)
__device__ float  g_pool[MTILES*PP];

// ---------------- PTX helpers ----------------------------------------------
__device__ __forceinline__ uint32_t smem_u32(const void* p){
    uint32_t a; asm("{ .reg .u64 t; cvta.to.shared.u64 t, %1; cvt.u32.u64 %0, t; }" : "=r"(a) : "l"(p));
    return a;
}
#define MBAR_INIT(mb, c)  asm volatile("mbarrier.init.shared.b64 [%0], %1;" :: "r"((uint32_t)(mb)), "r"((uint32_t)(c)) : "memory")
#define MBAR_EXPECT(mb, tx) asm volatile("mbarrier.arrive.expect_tx.shared.b64 _, [%0], %1;" :: "r"((uint32_t)(mb)), "r"((uint32_t)(tx)) : "memory")
#define MBAR_WAIT(mb, ph) do { \
    uint32_t _m = (uint32_t)(mb), _p = (uint32_t)(ph), _d; \
    asm volatile("{\n\t.reg .pred p;\n\tmbarrier.try_wait.parity.acquire.cta.shared::cta.b64 p, [%1], %2;\n\tselp.b32 %0, 1, 0, p;\n\t}" \
        : "=r"(_d) : "r"(_m), "r"(_p) : "memory"); \
    if (!_d) { \
        asm volatile("{\n\t.reg .pred P1;\n\tWL_%=:\n\tmbarrier.try_wait.parity.acquire.cta.shared::cta.b64 P1, [%0], %1, 0x989680;\n\t@P1 bra.uni WD_%=;\n\tbra.uni WL_%=;\n\tWD_%=:\n\t}" \
            :: "r"(_m), "r"(_p) : "memory"); \
    } } while(0)
#define BULK_G2S(dst, src, bytes, mb) \
    asm volatile("cp.async.bulk.shared::cluster.global.mbarrier::complete_tx::bytes [%0], [%1], %2, [%3];" \
        :: "r"((uint32_t)(dst)), "l"(src), "r"((uint32_t)(bytes)), "r"((uint32_t)(mb)) : "memory")

#define LDMX4(r, a) \
    asm volatile("ldmatrix.sync.aligned.m8n8.x4.shared.b16 {%0,%1,%2,%3}, [%4];" \
        : "=r"((r)[0]), "=r"((r)[1]), "=r"((r)[2]), "=r"((r)[3]) : "r"(a))

__device__ __forceinline__ void mma16816(float* c, const uint32_t* a, uint32_t b0, uint32_t b1){
    asm volatile("mma.sync.aligned.m16n8k16.row.col.f32.f16.f16.f32 "
        "{%0,%1,%2,%3}, {%4,%5,%6,%7}, {%8,%9}, {%0,%1,%2,%3};"
        : "+f"(c[0]), "+f"(c[1]), "+f"(c[2]), "+f"(c[3])
        : "r"(a[0]), "r"(a[1]), "r"(a[2]), "r"(a[3]), "r"(b0), "r"(b1));
}

__device__ __forceinline__ uint32_t tswz(int row, int g){
    return (uint32_t)(row*128 + (((g ^ (row & 7))) << 4));
}

// ---------------------------------------------------------------------------
// 1) Aggregation: LDS.128 gather (4 nodes/warp), direct __ldg(int4) indices.
//    z==zconv blocks convert weights (fp16) for BOTH layers. (unchanged R16)
// ---------------------------------------------------------------------------
#define AGG_SMEM 131072
__global__ __launch_bounds__(1024) void agg_k(const __half* __restrict__ Sh,
        const int* __restrict__ nf, const float* __restrict__ emb,
        const int* __restrict__ nn_idx, const float* __restrict__ mask,
        const float* __restrict__ W0, const float* __restrict__ W1,
        int D, int nch, int useEmb, int nsplit_shift, int zconv){
    extern __shared__ char smraw[];
    __half* sbuf = (__half*)smraw;                  // [1024][64]
    int tid = threadIdx.x, lane = tid & 31, w = tid >> 5;

    if ((int)blockIdx.z == zconv){
        int bid = blockIdx.x * gridDim.y + blockIdx.y;   // 0..31
        for (int t = bid*1024 + tid; t < 49152; t += 32*1024){
            const float* W; __half *Bh; int g;
            if (t < 16384){ W = W0; Bh = g_Bh0; g = t; }
            else          { W = W1; Bh = g_Bh1; g = t - 16384; }
            int n  = g & 255;
            int kq = g >> 8;
            __half hv[8];
            #pragma unroll
            for (int j = 0; j < 8; j++)
                hv[j] = __float2half(W[(size_t)(kq*8 + j)*HH + n]);
            int ch = kq >> 3;
            size_t byt = (((size_t)(ch*256 + n)) << 7) + ((((kq & 7) ^ (n & 7))) << 4);
            *(uint4*)((char*)Bh + byt) = *(uint4*)hv;
        }
        return;
    }

    int b   = blockIdx.x;
    int d0c = blockIdx.y * 64;

    if (useEmb){
        const int* nfb = nf + b*NN;
        for (int i = tid; i < NN*32; i += 1024){
            int row = i >> 5, cp = (i & 31) << 1;
            const float* ep = emb + (size_t)nfb[row]*D0 + d0c + cp;
            float2 v = make_float2(ep[0], ep[1]);
            *(__half2*)&sbuf[row*64 + cp] = __floats2half2_rn(v.x, v.y);
        }
    } else {
        const __half* Sb = Sh + (size_t)b*NN*HH;
        for (int i = tid; i < NN*16; i += 1024){
            int row = i >> 4, cp = (i & 15) << 2;
            *(uint2*)&sbuf[row*64 + cp] = *(const uint2*)&Sb[(size_t)row*HH + d0c + cp];
        }
    }
    __syncthreads();

    int nPer  = NN >> nsplit_shift;
    int nbase = blockIdx.z * nPer;
    char* Ag = (char*)g_Af;
    int p = lane & 7, grp = lane >> 3;

    for (int n0 = nbase + 4*w; n0 < nbase + nPer; n0 += 128){
        int nj = n0 + grp;
        const int4* ip4 = (const int4*)(nn_idx + (size_t)(b*NN + nj)*(KK*EE));
        const __half2* sp = (const __half2*)sbuf + p*4;

        __half2 acc[4][4];
        #pragma unroll
        for (int e = 0; e < 4; e++)
            #pragma unroll
            for (int i = 0; i < 4; i++) acc[e][i] = __float2half2_rn(0.f);

        #pragma unroll 4
        for (int g = 0; g < KK; g++){
            int4 q = __ldg(&ip4[g]);
            uint4 v0 = *(const uint4*)(sp + q.x*32);
            uint4 v1 = *(const uint4*)(sp + q.y*32);
            uint4 v2 = *(const uint4*)(sp + q.z*32);
            uint4 v3 = *(const uint4*)(sp + q.w*32);
            const __half2* h0 = (const __half2*)&v0;
            const __half2* h1 = (const __half2*)&v1;
            const __half2* h2 = (const __half2*)&v2;
            const __half2* h3 = (const __half2*)&v3;
            #pragma unroll
            for (int i = 0; i < 4; i++){
                acc[0][i] = __hadd2(acc[0][i], h0[i]);
                acc[1][i] = __hadd2(acc[1][i], h1[i]);
                acc[2][i] = __hadd2(acc[2][i], h2[i]);
                acc[3][i] = __hadd2(acc[3][i], h3[i]);
            }
        }

        __half2 m2 = __float2half2_rn(mask[b*NN + nj] * 0.0625f);
        int mtile = b*8 + (nj >> 7);
        int mrow  = nj & 127;
        size_t tbase = ((size_t)mtile*nch) << 14;
        uint32_t inrow = (((uint32_t)(p ^ (mrow & 7))) << 4);
        #pragma unroll
        for (int e = 0; e < EE; e++){
            __half2 r[4];
            #pragma unroll
            for (int i = 0; i < 4; i++) r[i] = __hmul2(acc[e][i], m2);
            int ch = (e*D + d0c) >> 6;
            *(uint4*)(Ag + tbase + (((size_t)ch*128 + mrow) << 7) + inrow) = *(uint4*)r;
        }
    }
}

// ---------------------------------------------------------------------------
// 2) GEMM: single-pass fp16, K-chunk 128 (2 stages x 96KB), 128x256 tile,
//    512 thr / 16 warps (warp tile 64x32), B-fragment double-buffering,
//    register-resident epilogue aliased into dead stage memory.
// ---------------------------------------------------------------------------
#define STG96 98304
// epilogue scratch aliases stage0 (dead after mainloop)
#define OFF_SSB  0           // [128][9] floats = 4608
#define OFF_INV  4608        // 128 floats
#define OFF_AB   5120        // 128 floats
#define OFF_WA   5632        // 256 floats
#define OFF_WT   6656        // 256*12 floats = 12288
#define OFF_ZW   18944       // [16][36] floats = 2304
#define OFF_ZF   21248       // 256 floats
#define MB_OFF   196608      // 2 mbars
#define GEMM_SMEM 196672

__global__ __launch_bounds__(512, 1) void gemm2_k(
        const __half* __restrict__ Agl, const __half* __restrict__ Bhg,
        int nch, const float* __restrict__ bias, __half* __restrict__ Sout,
        int fuse, const float* __restrict__ Wout, const float* __restrict__ bout,
        const float* __restrict__ Watt, const float* __restrict__ batt){
    extern __shared__ char smx[];
    uint32_t sb0 = smem_u32(smx);
    uint32_t mb  = sb0 + MB_OFF;
    int tid = threadIdx.x, lane = tid & 31, w = tid >> 5;
    int wm = w >> 3, wn = w & 7;
    int mtile = blockIdx.x;
    int nch2 = nch >> 1;                       // 128k chunks

    if (tid == 0){ MBAR_INIT(mb, 1); MBAR_INIT(mb + 8, 1); }
    __syncthreads();

    float c[4][4][4];
    #pragma unroll
    for (int mi = 0; mi < 4; mi++)
        #pragma unroll
        for (int nj = 0; nj < 4; nj++)
            #pragma unroll
            for (int q = 0; q < 4; q++) c[mi][nj][q] = 0.f;

    auto issue = [&](int c2){
        int st = c2 & 1;
        uint32_t d = sb0 + st*STG96;
        uint32_t m = mb + st*8;
        MBAR_EXPECT(m, STG96);
        BULK_G2S(d,         (const char*)Agl + ((size_t)(mtile*nch + 2*c2) << 14), 32768, m);
        BULK_G2S(d + 32768, (const char*)Bhg + ((size_t)(2*c2) << 15),             65536, m);
    };

    if (tid == 0){ issue(0); if (nch2 > 1) issue(1); }
    int ph[2] = {0, 0};

    int lrow = lane & 15;
    int ghalf = lane >> 4;
    for (int c2 = 0; c2 < nch2; c2++){
        int st = c2 & 1;
        MBAR_WAIT(mb + st*8, ph[st]); ph[st] ^= 1;

        uint32_t ab = sb0 + st*STG96;
        uint32_t bh = ab + 32768;

        uint32_t bq[2][2][4];                    // [nj][buf][4]
        {   // preload B frags for s=0
            LDMX4(bq[0][0], bh + tswz(wn*32 + lrow,      ghalf));
            LDMX4(bq[1][0], bh + tswz(wn*32 + 16 + lrow, ghalf));
        }
        #pragma unroll
        for (int s = 0; s < 8; s++){
            int cur = s & 1;
            if (s < 7){                          // prefetch B for s+1
                int kh2 = (s+1) >> 2;
                int gn  = 2*((s+1) & 3) + ghalf;
                uint32_t bb = bh + kh2*32768;
                LDMX4(bq[0][cur^1], bb + tswz(wn*32 + lrow,      gn));
                LDMX4(bq[1][cur^1], bb + tswz(wn*32 + 16 + lrow, gn));
            }
            int kh = s >> 2;
            int g  = 2*(s & 3) + ghalf;
            uint32_t aa = ab + kh*16384;
            uint32_t a[4][4];
            #pragma unroll
            for (int mi = 0; mi < 4; mi++)
                LDMX4(a[mi], aa + tswz(wm*64 + mi*16 + lrow, g));
            #pragma unroll
            for (int mi = 0; mi < 4; mi++)
                #pragma unroll
                for (int nj = 0; nj < 2; nj++){
                    mma16816(c[mi][2*nj+0], a[mi], bq[nj][cur][0], bq[nj][cur][2]);
                    mma16816(c[mi][2*nj+1], a[mi], bq[nj][cur][1], bq[nj][cur][3]);
                }
        }
        __syncthreads();
        if (tid == 0 && c2 + 2 < nch2) issue(c2 + 2);
    }

    // ---- register-resident epilogue (scratch aliases dead stage0) ----
    float* ssb  = (float*)(smx + OFF_SSB);
    float* invb = (float*)(smx + OFF_INV);
    float* ab_  = (float*)(smx + OFF_AB);
    float* wa   = (float*)(smx + OFF_WA);
    float* wt   = (float*)(smx + OFF_WT);
    int qr = lane >> 2, qc = (lane & 3)*2;

    float ssq[4][2];
    #pragma unroll
    for (int mi = 0; mi < 4; mi++){ ssq[mi][0] = 0.f; ssq[mi][1] = 0.f; }
    #pragma unroll
    for (int mi = 0; mi < 4; mi++)
        #pragma unroll
        for (int nj = 0; nj < 4; nj++){
            int col = wn*32 + nj*8 + qc;
            float b0 = bias[col], b1 = bias[col+1];
            #pragma unroll
            for (int qh = 0; qh < 2; qh++){
                float h0 = fmaxf(c[mi][nj][2*qh+0] + b0, 0.f);
                float h1 = fmaxf(c[mi][nj][2*qh+1] + b1, 0.f);
                c[mi][nj][2*qh+0] = h0;
                c[mi][nj][2*qh+1] = h1;
                ssq[mi][qh] += h0*h0 + h1*h1;
            }
        }
    #pragma unroll
    for (int mi = 0; mi < 4; mi++)
        #pragma unroll
        for (int qh = 0; qh < 2; qh++){
            float v = ssq[mi][qh];
            v += __shfl_xor_sync(0xffffffffu, v, 1);
            v += __shfl_xor_sync(0xffffffffu, v, 2);
            if ((lane & 3) == 0)
                ssb[(wm*64 + mi*16 + qr + 8*qh)*9 + wn] = v;
        }
    if (fuse){
        if (tid < 256) wa[tid] = Watt[tid];
        for (int i = tid; i < 256*PP; i += 512){
            int d = i / PP, p2 = i - d*PP;
            wt[d*12 + p2] = Wout[i];
        }
    }
    __syncthreads();
    if (tid < 128){
        float s = 0.f;
        #pragma unroll
        for (int j = 0; j < 8; j++) s += ssb[tid*9 + j];
        invb[tid] = 1.0f/(sqrtf(s) + EPSF);
    }
    __syncthreads();

    int m0 = mtile*128;
    if (!fuse){
        #pragma unroll
        for (int mi = 0; mi < 4; mi++)
            #pragma unroll
            for (int qh = 0; qh < 2; qh++){
                int row = wm*64 + mi*16 + qr + 8*qh;
                float inv = invb[row];
                __half* op = Sout + (size_t)(m0 + row)*HH;
                #pragma unroll
                for (int nj = 0; nj < 4; nj++){
                    int col = wn*32 + nj*8 + qc;
                    *(__half2*)(op + col) =
                        __floats2half2_rn(c[mi][nj][2*qh]*inv, c[mi][nj][2*qh+1]*inv);
                }
            }
    } else {
        float* zw = (float*)(smx + OFF_ZW);
        float* zf = (float*)(smx + OFF_ZF);
        #pragma unroll
        for (int mi = 0; mi < 4; mi++)
            #pragma unroll
            for (int qh = 0; qh < 2; qh++){
                int row = wm*64 + mi*16 + qr + 8*qh;
                float at = 0.f;
                #pragma unroll
                for (int nj = 0; nj < 4; nj++){
                    int col = wn*32 + nj*8 + qc;
                    at += c[mi][nj][2*qh]*wa[col] + c[mi][nj][2*qh+1]*wa[col+1];
                }
                at += __shfl_xor_sync(0xffffffffu, at, 1);
                at += __shfl_xor_sync(0xffffffffu, at, 2);
                if ((lane & 3) == 0) ssb[row*9 + wn] = at;
            }
        __syncthreads();
        if (tid < 128){
            float at = 0.f;
            #pragma unroll
            for (int j = 0; j < 8; j++) at += ssb[tid*9 + j];
            ab_[tid] = 1.0f/(1.0f + expf(-(invb[tid]*at + batt[0])));
        }
        __syncthreads();
        float2 z2[4];
        #pragma unroll
        for (int nj = 0; nj < 4; nj++) z2[nj] = make_float2(0.f, 0.f);
        #pragma unroll
        for (int mi = 0; mi < 4; mi++)
            #pragma unroll
            for (int qh = 0; qh < 2; qh++){
                int row = wm*64 + mi*16 + qr + 8*qh;
                float cf = ab_[row]*invb[row];
                #pragma unroll
                for (int nj = 0; nj < 4; nj++){
                    z2[nj].x += cf*c[mi][nj][2*qh];
                    z2[nj].y += cf*c[mi][nj][2*qh+1];
                }
            }
        #pragma unroll
        for (int nj = 0; nj < 4; nj++){
            #pragma unroll
            for (int off = 4; off < 32; off <<= 1){
                z2[nj].x += __shfl_xor_sync(0xffffffffu, z2[nj].x, off);
                z2[nj].y += __shfl_xor_sync(0xffffffffu, z2[nj].y, off);
            }
        }
        if (lane < 4){
            #pragma unroll
            for (int nj = 0; nj < 4; nj++)
                *(float2*)&zw[w*36 + nj*8 + lane*2] = z2[nj];
        }
        __syncthreads();
        if (tid < 256){
            int wn2 = tid >> 5, cc = tid & 31;
            zf[tid] = zw[(wn2)*36 + cc] + zw[(8 + wn2)*36 + cc];
        }
        __syncthreads();
        if (tid < PP){
            float A = 0.f;
            #pragma unroll
            for (int r = 0; r < 128; r++) A += ab_[r];
            float sc = A * bout[tid];
            for (int d = 0; d < 256; d++) sc += zf[d] * wt[d*12 + tid];
            g_pool[mtile*PP + tid] = sc;
        }
    }
}

// ---------------------------------------------------------------------------
// 3) Final reduce
// ---------------------------------------------------------------------------
__global__ void reduce_k(float* __restrict__ out){
    int i = threadIdx.x;
    if (i < BB*PP){
        int b = i / PP, p = i - b*PP;
        float s = 0.f;
        #pragma unroll
        for (int seg = 0; seg < 8; seg++) s += g_pool[(b*8 + seg)*PP + p];
        out[i] = s * (1.0f/NN);
    }
}

// ---------------------------------------------------------------------------
extern "C" void kernel_launch(void* const* d_in, const int* in_sizes, int n_in,
                              void* d_out, int out_size){
    (void)in_sizes; (void)n_in; (void)out_size;
    const int*   nf   = (const int*)  d_in[0];
    const int*   nn   = (const int*)  d_in[1];
    const float* mask = (const float*)d_in[2];
    const float* emb  = (const float*)d_in[3];
    const float* W0   = (const float*)d_in[4];
    const float* b0   = (const float*)d_in[5];
    const float* W1   = (const float*)d_in[6];
    const float* b1   = (const float*)d_in[7];
    const float* Wout = (const float*)d_in[8];
    const float* bout = (const float*)d_in[9];
    const float* Watt = (const float*)d_in[10];
    const float* batt = (const float*)d_in[11];
    float* out = (float*)d_out;

    __half *stateh, *af, *bh0, *bh1;
    cudaGetSymbolAddress((void**)&stateh, g_stateh);
    cudaGetSymbolAddress((void**)&af,  g_Af);
    cudaGetSymbolAddress((void**)&bh0, g_Bh0);
    cudaGetSymbolAddress((void**)&bh1, g_Bh1);

    cudaFuncSetAttribute(agg_k,   cudaFuncAttributeMaxDynamicSharedMemorySize, AGG_SMEM);
    cudaFuncSetAttribute(gemm2_k, cudaFuncAttributeMaxDynamicSharedMemorySize, GEMM_SMEM);

    // Layer 0 (Kd=512, nch=8): embed fused, z-split 4; z==4 converts weights
    agg_k<<<dim3(BB, D0/64, 5), 1024, AGG_SMEM>>>(stateh, nf, emb, nn, mask,
                                                  W0, W1, D0, 8, 1, 2, 4);
    gemm2_k<<<MTILES, 512, GEMM_SMEM>>>(af, bh0, 8, b0, stateh,
                                        0, nullptr, nullptr, nullptr, nullptr);

    // Layer 1 (Kd=1024, nch=16): z-split 2; fused output head
    agg_k<<<dim3(BB, HH/64, 2), 1024, AGG_SMEM>>>(stateh, nf, emb, nn, mask,
                                                  W0, W1, HH, 16, 0, 1, -1);
    gemm2_k<<<MTILES, 512, GEMM_SMEM>>>(af, bh1, 16, b1, stateh,
                                        1, Wout, bout, Watt, batt);

    reduce_k<<<1, 192>>>(out);
}